// round 1
// baseline (speedup 1.0000x reference)
#include <cuda_runtime.h>
#include <cstddef>

// Problem constants (fixed by the dataset problem)
#define CC 32
#define HH 128
#define WW 512
#define PAD 40
#define DD (PAD + 1)

// out[c,d,h,w] = in1[c,h,w] * (w >= d ? in2[c,h,w-d] : 0)
// One block per (c,d,h) row; 128 threads x float4 = 512 elements.
__global__ __launch_bounds__(128) void corr1d_kernel(
    const float* __restrict__ in1,
    const float* __restrict__ in2,
    float* __restrict__ out)
{
    const int row = blockIdx.x;           // row in [0, C*D*H)
    const int h  = row % HH;
    const int cd = row / HH;
    const int d  = cd % DD;
    const int c  = cd / DD;

    const float* p1 = in1 + ((size_t)(c * HH + h)) * WW;
    const float* p2 = in2 + ((size_t)(c * HH + h)) * WW;
    float* po = out + (size_t)row * WW;

    const int w = threadIdx.x * 4;        // 0..508

    // aligned 128-bit load of in1
    const float4 a = *reinterpret_cast<const float4*>(p1 + w);

    // d-shifted in2 loads (misaligned by d); predicate for w-d < 0
    const int s = w - d;
    float b0 = (s + 0 >= 0) ? __ldg(p2 + s + 0) : 0.0f;
    float b1 = (s + 1 >= 0) ? __ldg(p2 + s + 1) : 0.0f;
    float b2 = (s + 2 >= 0) ? __ldg(p2 + s + 2) : 0.0f;
    float b3 = (s + 3 >= 0) ? __ldg(p2 + s + 3) : 0.0f;

    float4 r;
    r.x = a.x * b0;
    r.y = a.y * b1;
    r.z = a.z * b2;
    r.w = a.w * b3;

    *reinterpret_cast<float4*>(po + w) = r;   // aligned 128-bit store
}

extern "C" void kernel_launch(void* const* d_in, const int* in_sizes, int n_in,
                              void* d_out, int out_size)
{
    const float* in1 = (const float*)d_in[0];
    const float* in2 = (const float*)d_in[1];
    float* out = (float*)d_out;

    const int rows = CC * DD * HH;        // 167,936 blocks
    corr1d_kernel<<<rows, WW / 4>>>(in1, in2, out);
}

// round 2
// speedup vs baseline: 1.5531x; 1.5531x over previous
#include <cuda_runtime.h>
#include <cstddef>

// Problem constants (fixed by the dataset problem)
#define CC 32
#define HH 128
#define WW 512
#define PAD 40
#define DD (PAD + 1)

// out[c,d,h,w] = in1[c,h,w] * (w >= d ? in2[c,h,w-d] : 0)
//
// One CTA per (c,h) row (4096 CTAs, 128 threads). The in2 row is staged once
// into shared memory with a PAD-float zero apron on the left, so the shifted
// read s2[PAD + w - d] is branchless and always in-bounds. Each thread owns an
// aligned float4 of the row (w = 4t); across the d-loop the needed in2 window
// slides left by one float per iteration, so we keep it in 4 rotating
// registers and load only ONE new scalar from shared per iteration.
__global__ __launch_bounds__(128) void corr1d_row_kernel(
    const float* __restrict__ in1,
    const float* __restrict__ in2,
    float* __restrict__ out)
{
    __shared__ float s2[PAD + WW];   // 552 floats; [0,PAD) is the zero apron

    const int row = blockIdx.x;      // (c,h) in [0, C*H)
    const int t   = threadIdx.x;     // 0..127
    const int c   = row / HH;
    const int h   = row % HH;

    // Stage rows. PAD*4 = 160 bytes, 16B-aligned, so float4 stores into
    // (s2 + PAD) are legal.
    const float4 a = reinterpret_cast<const float4*>(in1 + (size_t)row * WW)[t];
    if (t < PAD) s2[t] = 0.0f;
    reinterpret_cast<float4*>(s2 + PAD)[t] =
        reinterpret_cast<const float4*>(in2 + (size_t)row * WW)[t];
    __syncthreads();

    // Output base for d=0 plane of this (c,h) row; planes are HH*WW apart.
    float4* po = reinterpret_cast<float4*>(
        out + ((size_t)(c * DD) * HH + h) * WW) + t;
    const size_t plane_stride_v4 = (size_t)HH * WW / 4;   // 16384 float4s

    // d=0 window: one aligned LDS.128.
    float4 b = reinterpret_cast<const float4*>(s2 + PAD)[t];
    float b0 = b.x, b1 = b.y, b2 = b.z, b3 = b.w;

    const int base = PAD + 4 * t;    // index of b0 at d=0

    #pragma unroll
    for (int d = 0; d <= PAD; ++d) {
        float4 r;
        r.x = a.x * b0;
        r.y = a.y * b1;
        r.z = a.z * b2;
        r.w = a.w * b3;
        po[(size_t)d * plane_stride_v4] = r;

        // Slide the window left by one for the next disparity.
        if (d < PAD) {
            b3 = b2;
            b2 = b1;
            b1 = b0;
            b0 = s2[base - d - 1];
        }
    }
}

extern "C" void kernel_launch(void* const* d_in, const int* in_sizes, int n_in,
                              void* d_out, int out_size)
{
    const float* in1 = (const float*)d_in[0];
    const float* in2 = (const float*)d_in[1];
    float* out = (float*)d_out;

    corr1d_row_kernel<<<CC * HH, WW / 4>>>(in1, in2, out);
}

// round 3
// speedup vs baseline: 1.6819x; 1.0829x over previous
#include <cuda_runtime.h>
#include <cstddef>

// Problem constants (fixed by the dataset problem)
#define CC 32
#define HH 128
#define WW 512
#define PAD 40
#define DD (PAD + 1)

// out[c,d,h,w] = in1[c,h,w] * (w >= d ? in2[c,h,w-d] : 0)
//
// One CTA per (c,h) row (4096 CTAs, 128 threads). The in2 row is staged once
// into shared memory with a PAD-float zero apron, then each thread preloads
// its entire 44-float shifted window into registers (11 conflict-free
// LDS.128). The fully-unrolled d-loop is then pure FMUL + streaming STG.128
// with no shared-memory access and no cross-iteration dependencies, so all
// 41 stores can be issued back-to-back (max store-queue MLP).
__global__ __launch_bounds__(128) void corr1d_row_kernel(
    const float* __restrict__ in1,
    const float* __restrict__ in2,
    float* __restrict__ out)
{
    __shared__ float s2[PAD + WW];   // 552 floats; [0,PAD) is the zero apron

    const int row = blockIdx.x;      // (c,h) in [0, C*H)
    const int t   = threadIdx.x;     // 0..127
    const int c   = row / HH;
    const int h   = row % HH;

    // Stage rows. PAD*4 = 160 bytes, 16B-aligned, so float4 stores into
    // (s2 + PAD) are legal.
    const float4 a = reinterpret_cast<const float4*>(in1 + (size_t)row * WW)[t];
    if (t < PAD) s2[t] = 0.0f;
    reinterpret_cast<float4*>(s2 + PAD)[t] =
        reinterpret_cast<const float4*>(in2 + (size_t)row * WW)[t];
    __syncthreads();

    // Preload the full shifted window into registers.
    // Thread t owns outputs w = 4t..4t+3. Across d = 0..PAD it needs
    // s2[PAD + 4t - PAD .. PAD + 4t + 3] = s2[4t .. 4t + 43]  (44 floats).
    // 11 float4 loads at s2 + 4*(t+k): 16B-aligned, conflict-free.
    float W[44];
    #pragma unroll
    for (int k = 0; k < 11; ++k) {
        const float4 v = reinterpret_cast<const float4*>(s2)[t + k];
        W[4 * k + 0] = v.x;
        W[4 * k + 1] = v.y;
        W[4 * k + 2] = v.z;
        W[4 * k + 3] = v.w;
    }

    // Output base for d=0 plane of this (c,h) row; planes are HH*WW apart.
    float4* po = reinterpret_cast<float4*>(
        out + ((size_t)(c * DD) * HH + h) * WW) + t;
    const size_t plane_stride_v4 = (size_t)HH * WW / 4;   // 16384 float4s

    // For plane d, b_j = s2[PAD + 4t + j - d] = W[40 + j - d].
    #pragma unroll
    for (int d = 0; d <= PAD; ++d) {
        float4 r;
        r.x = a.x * W[40 - d];
        r.y = a.y * W[41 - d];
        r.z = a.z * W[42 - d];
        r.w = a.w * W[43 - d];
        // Streaming (evict-first) store: output is write-once, never read.
        __stcs(po + (size_t)d * plane_stride_v4, r);
    }
}

extern "C" void kernel_launch(void* const* d_in, const int* in_sizes, int n_in,
                              void* d_out, int out_size)
{
    const float* in1 = (const float*)d_in[0];
    const float* in2 = (const float*)d_in[1];
    float* out = (float*)d_out;

    corr1d_row_kernel<<<CC * HH, WW / 4>>>(in1, in2, out);
}